// round 15
// baseline (speedup 1.0000x reference)
#include <cuda_runtime.h>
#include <cstdint>

// YOLOv7 P3 head: B=16, A=3, C=85/anchor, H=W=80, stride 8.
// Input:  [b, a, ch(85), h, w]   Output: [b, a*h*w, 85]
//
// Final structure (= R8, best measured): 512-thread block, 128-position tile,
// output-layout smem (43.5KB), __launch_bounds__(512,4) -> 64 warps/SM,
// regs<=32 (3+3 split LDG.128 prefetch).
// A/B vs R8: input loads use default L2 policy (__ldg) instead of __ldcs.
// Warp w: s = w&3 (position quarter), g0 = w>>2. Lane: c = lane>>3, qq = lane&7.
// STS bank = (20*qq + c + const) mod 32 -> conflict-free scatter.
// Per-quarter named barrier then 10880B TMA bulk store (L2 evict_first).

#define B_       16
#define A_       3
#define C_       85
#define W_       80
#define HW_      6400
#define TILE_    128
#define THREADS_ 512
#define QTR_BYTES_ (32 * C_ * 4)   // 10880

__device__ __forceinline__ float sigm(float x) {
    float t;
    const float h = 0.5f * x;
    asm("tanh.approx.f32 %0, %1;" : "=f"(t) : "f"(h));   // 1 MUFU
    return fmaf(0.5f, t, 0.5f);
}

__global__ __launch_bounds__(THREADS_, 4)
void yolo_head_kernel(const float* __restrict__ in,
                      const float* __restrict__ anchors,
                      float* __restrict__ out)
{
    __shared__ alignas(128) float sbuf[TILE_ * C_];   // 43520 B

    const int tilesPerBA = HW_ / TILE_;      // 50
    const int bid  = blockIdx.x;
    const int ba   = bid / tilesPerBA;       // b*A + a
    const int tile = bid - ba * tilesPerBA;
    const int pos0 = tile * TILE_;
    const int a    = ba % A_;

    const float aw = __ldg(&anchors[a * 2 + 0]);
    const float ah = __ldg(&anchors[a * 2 + 1]);

    const int tid  = threadIdx.x;
    const int w    = tid >> 5;               // 0..15
    const int lane = tid & 31;
    const int c    = lane >> 3;              // 0..3
    const int qq   = lane & 7;               // 0..7
    const int s    = w & 3;                  // position quarter
    const int g0   = w >> 2;                 // 0..3
    const int p    = (s * 8 + qq) * 4;       // local position base 0..124
    const int ch0  = g0 * 4 + c;             // 0..15
    const bool tailValid = (ch0 <= 4);       // ch0+80 <= 84

    const float* tptr = in + (size_t)ba * (C_ * HW_) + pos0
                           + (size_t)ch0 * HW_ + p;

    float vv[4];

    // ---- batch 0: k = 0..2  (ch = ch0 + 16k) ----
    {
        float4 r[3];
        #pragma unroll
        for (int k = 0; k < 3; k++)
            r[k] = __ldg(reinterpret_cast<const float4*>(tptr + (size_t)k * (16 * HW_)));

        #pragma unroll
        for (int k = 0; k < 3; k++) {
            const int ch = ch0 + 16 * k;
            vv[0] = r[k].x; vv[1] = r[k].y; vv[2] = r[k].z; vv[3] = r[k].w;

            if (k == 0 && ch < 4) {          // only warps 0..3 (g0==0), once
                if (ch == 0) {
                    const int gp = pos0 + p;
                    #pragma unroll
                    for (int j = 0; j < 4; j++)
                        vv[j] = (sigm(vv[j]) + (float)((gp + j) % W_)) * 8.0f;
                } else if (ch == 1) {
                    const int gp = pos0 + p;
                    #pragma unroll
                    for (int j = 0; j < 4; j++)
                        vv[j] = (sigm(vv[j]) + (float)((gp + j) / W_)) * 8.0f;
                } else {
                    const float sc = (ch == 2) ? aw : ah;
                    #pragma unroll
                    for (int j = 0; j < 4; j++) {
                        const float cl = fminf(fmaxf(vv[j], -16.0f), 16.0f);
                        vv[j] = __expf(cl) * sc;
                    }
                }
            } else {
                #pragma unroll
                for (int j = 0; j < 4; j++) vv[j] = sigm(vv[j]);
            }
            // bank = (20*qq + c + const) mod 32 -> conflict-free
            #pragma unroll
            for (int j = 0; j < 4; j++) sbuf[(p + j) * C_ + ch] = vv[j];
        }
    }

    // ---- batch 1: k = 3..5  (k=5 valid iff ch0 <= 4) ----
    {
        float4 r[3];
        #pragma unroll
        for (int k = 0; k < 2; k++)
            r[k] = __ldg(reinterpret_cast<const float4*>(tptr + (size_t)(k + 3) * (16 * HW_)));
        if (tailValid)
            r[2] = __ldg(reinterpret_cast<const float4*>(tptr + (size_t)5 * (16 * HW_)));

        #pragma unroll
        for (int k = 0; k < 3; k++) {
            if (k == 2 && !tailValid) break;
            const int ch = ch0 + 16 * (k + 3);   // >= 48: generic path
            vv[0] = r[k].x; vv[1] = r[k].y; vv[2] = r[k].z; vv[3] = r[k].w;
            #pragma unroll
            for (int j = 0; j < 4; j++) vv[j] = sigm(vv[j]);
            #pragma unroll
            for (int j = 0; j < 4; j++) sbuf[(p + j) * C_ + ch] = vv[j];
        }
    }

    // ---- per-quarter named barrier (4 warps = 128 threads), then TMA store
    asm volatile("bar.sync %0, 128;" :: "r"(s + 1) : "memory");

    if (lane == 0 && w < 4) {                // warp q issues quarter q (q == s)
        float* outBase = out + ((size_t)(ba * HW_ + pos0) + w * 32) * C_;
        const float* src = sbuf + w * 32 * C_;
        uint32_t saddr;
        asm("{ .reg .u64 t; cvta.to.shared.u64 t, %1; cvt.u32.u64 %0, t; }"
            : "=r"(saddr) : "l"(src));
        uint64_t pol;
        asm("createpolicy.fractional.L2::evict_first.b64 %0, 1.0;" : "=l"(pol));
        asm volatile("fence.proxy.async.shared::cta;" ::: "memory");
        asm volatile(
            "cp.async.bulk.global.shared::cta.bulk_group.L2::cache_hint "
            "[%0], [%1], %2, %3;"
            :: "l"(outBase), "r"(saddr), "r"((uint32_t)QTR_BYTES_), "l"(pol)
            : "memory");
        asm volatile("cp.async.bulk.commit_group;" ::: "memory");
        asm volatile("cp.async.bulk.wait_group.read 0;" ::: "memory");
    }
}

extern "C" void kernel_launch(void* const* d_in, const int* in_sizes, int n_in,
                              void* d_out, int out_size) {
    const float* in      = (const float*)d_in[0];
    const float* anchors = (const float*)d_in[1];
    float* out           = (float*)d_out;

    const int blocks = B_ * A_ * (HW_ / TILE_);   // 2400
    yolo_head_kernel<<<blocks, THREADS_>>>(in, anchors, out);
}

// round 16
// speedup vs baseline: 1.0263x; 1.0263x over previous
#include <cuda_runtime.h>
#include <cstdint>

// YOLOv7 P3 head: B=16, A=3, C=85/anchor, H=W=80, stride 8.
// Input:  [b, a, ch(85), h, w]   Output: [b, a*h*w, 85]
//
// FINAL (best measured, = R8): 512-thread block, 128-position tile,
// output-layout smem (43.5KB), __launch_bounds__(512,4) -> 4 CTAs x 16 warps
// = 64 warps/SM, regs<=32 (3+3 split LDG.128 __ldcs prefetch).
// Warp w: s = w&3 (position quarter), g0 = w>>2. Lane: c = lane>>3, qq = lane&7.
// STS bank = (20*qq + c + const) mod 32 -> conflict-free scatter.
// Per-quarter named barrier (4 warps = 128 thr) then 10880B TMA bulk store
// with L2 evict_first policy. Grid = 2400.

#define B_       16
#define A_       3
#define C_       85
#define W_       80
#define HW_      6400
#define TILE_    128
#define THREADS_ 512
#define QTR_BYTES_ (32 * C_ * 4)   // 10880

__device__ __forceinline__ float sigm(float x) {
    float t;
    const float h = 0.5f * x;
    asm("tanh.approx.f32 %0, %1;" : "=f"(t) : "f"(h));   // 1 MUFU
    return fmaf(0.5f, t, 0.5f);
}

__global__ __launch_bounds__(THREADS_, 4)
void yolo_head_kernel(const float* __restrict__ in,
                      const float* __restrict__ anchors,
                      float* __restrict__ out)
{
    __shared__ alignas(128) float sbuf[TILE_ * C_];   // 43520 B

    const int tilesPerBA = HW_ / TILE_;      // 50
    const int bid  = blockIdx.x;
    const int ba   = bid / tilesPerBA;       // b*A + a
    const int tile = bid - ba * tilesPerBA;
    const int pos0 = tile * TILE_;
    const int a    = ba % A_;

    const float aw = __ldg(&anchors[a * 2 + 0]);
    const float ah = __ldg(&anchors[a * 2 + 1]);

    const int tid  = threadIdx.x;
    const int w    = tid >> 5;               // 0..15
    const int lane = tid & 31;
    const int c    = lane >> 3;              // 0..3
    const int qq   = lane & 7;               // 0..7
    const int s    = w & 3;                  // position quarter
    const int g0   = w >> 2;                 // 0..3
    const int p    = (s * 8 + qq) * 4;       // local position base 0..124
    const int ch0  = g0 * 4 + c;             // 0..15
    const bool tailValid = (ch0 <= 4);       // ch0+80 <= 84

    const float* tptr = in + (size_t)ba * (C_ * HW_) + pos0
                           + (size_t)ch0 * HW_ + p;

    float vv[4];

    // ---- batch 0: k = 0..2  (ch = ch0 + 16k) ----
    {
        float4 r[3];
        #pragma unroll
        for (int k = 0; k < 3; k++)
            r[k] = __ldcs(reinterpret_cast<const float4*>(tptr + (size_t)k * (16 * HW_)));

        #pragma unroll
        for (int k = 0; k < 3; k++) {
            const int ch = ch0 + 16 * k;
            vv[0] = r[k].x; vv[1] = r[k].y; vv[2] = r[k].z; vv[3] = r[k].w;

            if (k == 0 && ch < 4) {          // only warps 0..3 (g0==0), once
                if (ch == 0) {
                    const int gp = pos0 + p;
                    #pragma unroll
                    for (int j = 0; j < 4; j++)
                        vv[j] = (sigm(vv[j]) + (float)((gp + j) % W_)) * 8.0f;
                } else if (ch == 1) {
                    const int gp = pos0 + p;
                    #pragma unroll
                    for (int j = 0; j < 4; j++)
                        vv[j] = (sigm(vv[j]) + (float)((gp + j) / W_)) * 8.0f;
                } else {
                    const float sc = (ch == 2) ? aw : ah;
                    #pragma unroll
                    for (int j = 0; j < 4; j++) {
                        const float cl = fminf(fmaxf(vv[j], -16.0f), 16.0f);
                        vv[j] = __expf(cl) * sc;
                    }
                }
            } else {
                #pragma unroll
                for (int j = 0; j < 4; j++) vv[j] = sigm(vv[j]);
            }
            // bank = (20*qq + c + const) mod 32 -> conflict-free
            #pragma unroll
            for (int j = 0; j < 4; j++) sbuf[(p + j) * C_ + ch] = vv[j];
        }
    }

    // ---- batch 1: k = 3..5  (k=5 valid iff ch0 <= 4) ----
    {
        float4 r[3];
        #pragma unroll
        for (int k = 0; k < 2; k++)
            r[k] = __ldcs(reinterpret_cast<const float4*>(tptr + (size_t)(k + 3) * (16 * HW_)));
        if (tailValid)
            r[2] = __ldcs(reinterpret_cast<const float4*>(tptr + (size_t)5 * (16 * HW_)));

        #pragma unroll
        for (int k = 0; k < 3; k++) {
            if (k == 2 && !tailValid) break;
            const int ch = ch0 + 16 * (k + 3);   // >= 48: generic path
            vv[0] = r[k].x; vv[1] = r[k].y; vv[2] = r[k].z; vv[3] = r[k].w;
            #pragma unroll
            for (int j = 0; j < 4; j++) vv[j] = sigm(vv[j]);
            #pragma unroll
            for (int j = 0; j < 4; j++) sbuf[(p + j) * C_ + ch] = vv[j];
        }
    }

    // ---- per-quarter named barrier (4 warps = 128 threads), then TMA store
    asm volatile("bar.sync %0, 128;" :: "r"(s + 1) : "memory");

    if (lane == 0 && w < 4) {                // warp q issues quarter q (q == s)
        float* outBase = out + ((size_t)(ba * HW_ + pos0) + w * 32) * C_;
        const float* src = sbuf + w * 32 * C_;
        uint32_t saddr;
        asm("{ .reg .u64 t; cvta.to.shared.u64 t, %1; cvt.u32.u64 %0, t; }"
            : "=r"(saddr) : "l"(src));
        uint64_t pol;
        asm("createpolicy.fractional.L2::evict_first.b64 %0, 1.0;" : "=l"(pol));
        asm volatile("fence.proxy.async.shared::cta;" ::: "memory");
        asm volatile(
            "cp.async.bulk.global.shared::cta.bulk_group.L2::cache_hint "
            "[%0], [%1], %2, %3;"
            :: "l"(outBase), "r"(saddr), "r"((uint32_t)QTR_BYTES_), "l"(pol)
            : "memory");
        asm volatile("cp.async.bulk.commit_group;" ::: "memory");
        asm volatile("cp.async.bulk.wait_group.read 0;" ::: "memory");
    }
}

extern "C" void kernel_launch(void* const* d_in, const int* in_sizes, int n_in,
                              void* d_out, int out_size) {
    const float* in      = (const float*)d_in[0];
    const float* anchors = (const float*)d_in[1];
    float* out           = (float*)d_out;

    const int blocks = B_ * A_ * (HW_ / TILE_);   // 2400
    yolo_head_kernel<<<blocks, THREADS_>>>(in, anchors, out);
}